// round 6
// baseline (speedup 1.0000x reference)
#include <cuda_runtime.h>
#include <cuda_bf16.h>

// Per-node precomputed scores. __device__ globals are the sanctioned scratch.
#define MAX_NODES 65536
__device__ float g_uscore[MAX_NODES];   // includes +b folded in
__device__ float g_iscore[MAX_NODES];

// ---------------------------------------------------------------------------
// Kernel 1: per-node dot products. One warp per TWO node rows (ILP=2).
// g_uscore[r] = dot(user_feats[r], W[0:128]) + b   (b folded here)
// g_iscore[r] = dot(item_feats[r], W[128:256])
// ---------------------------------------------------------------------------
__global__ void node_score_kernel(const float* __restrict__ user_feats,
                                  const float* __restrict__ item_feats,
                                  const float* __restrict__ W,
                                  const float* __restrict__ b,
                                  int Nu, int Ni)
{
    const int warps_per_block = blockDim.x >> 5;
    const int warp = blockIdx.x * warps_per_block + (threadIdx.x >> 5);
    const int lane = threadIdx.x & 31;
    const int total = Nu + Ni;

    const int row0 = warp * 2;
    const int row1 = row0 + 1;
    if (row0 >= total) return;

    const float4* Wu = reinterpret_cast<const float4*>(W);   // W[0:128]
    const float4* Wi = Wu + 32;                               // W[128:256]

    const float4* f0;
    const float4* w0;
    if (row0 < Nu) {
        f0 = reinterpret_cast<const float4*>(user_feats) + (size_t)row0 * 32;
        w0 = Wu;
    } else {
        f0 = reinterpret_cast<const float4*>(item_feats) + (size_t)(row0 - Nu) * 32;
        w0 = Wi;
    }

    const bool has1 = (row1 < total);
    const float4* f1 = f0;
    const float4* w1 = w0;
    if (has1) {
        if (row1 < Nu) {
            f1 = reinterpret_cast<const float4*>(user_feats) + (size_t)row1 * 32;
            w1 = Wu;
        } else {
            f1 = reinterpret_cast<const float4*>(item_feats) + (size_t)(row1 - Nu) * 32;
            w1 = Wi;
        }
    }

    const float4 v0 = f0[lane];
    const float4 v1 = f1[lane];
    const float4 a0 = w0[lane];
    const float4 a1 = w1[lane];

    float s0 = v0.x * a0.x + v0.y * a0.y + v0.z * a0.z + v0.w * a0.w;
    float s1 = v1.x * a1.x + v1.y * a1.y + v1.z * a1.z + v1.w * a1.w;

    #pragma unroll
    for (int o = 16; o > 0; o >>= 1) {
        s0 += __shfl_xor_sync(0xffffffffu, s0, o);
        s1 += __shfl_xor_sync(0xffffffffu, s1, o);
    }

    if (lane == 0) {
        const float bias = b[0];
        if (row0 < Nu) g_uscore[row0]      = s0 + bias;
        else           g_iscore[row0 - Nu] = s0;
        if (has1) {
            if (row1 < Nu) g_uscore[row1]      = s1 + bias;
            else           g_iscore[row1 - Nu] = s1;
        }
    }
}

// ---------------------------------------------------------------------------
// Kernel 2 (primary): u-table staged in dynamic shared memory (Nu*4 bytes),
// persistent 148 blocks. u-gather becomes LDS (bank-conflict cost only),
// v-gather remains L2. out = s_u[src] + g_iscore[dst]   (b already in u).
// ---------------------------------------------------------------------------
__global__ void edge_score_smem(const int2* __restrict__ src2,
                                const int2* __restrict__ dst2,
                                const int*  __restrict__ src_idx,
                                const int*  __restrict__ dst_idx,
                                float* __restrict__ out,
                                int Nu, int E2, int E)
{
    extern __shared__ float s_u[];

    // Stage u-table: Nu is divisible by 4 in this problem; handle remainder anyway.
    {
        const int n4 = Nu >> 2;
        const float4* src = reinterpret_cast<const float4*>(g_uscore);
        float4* dst = reinterpret_cast<float4*>(s_u);
        for (int i = threadIdx.x; i < n4; i += blockDim.x)
            dst[i] = src[i];
        for (int i = (n4 << 2) + threadIdx.x; i < Nu; i += blockDim.x)
            s_u[i] = g_uscore[i];
    }
    __syncthreads();

    const int tid = blockIdx.x * blockDim.x + threadIdx.x;
    const int stride = gridDim.x * blockDim.x;

    float2* out2 = reinterpret_cast<float2*>(out);
    for (int i = tid; i < E2; i += stride) {
        const int2 s = src2[i];
        const int2 d = dst2[i];
        const float v0 = g_iscore[d.x];
        const float v1 = g_iscore[d.y];
        float2 r;
        r.x = s_u[s.x] + v0;
        r.y = s_u[s.y] + v1;
        out2[i] = r;
    }

    // Odd-E tail (single element).
    if (tid == 0 && (E & 1)) {
        const int e = E - 1;
        out[e] = s_u[src_idx[e]] + g_iscore[dst_idx[e]];
    }
}

// ---------------------------------------------------------------------------
// Kernel 2 (fallback, if Nu too large for smem): plain 2-edge/thread gather.
// ---------------------------------------------------------------------------
__global__ void edge_score_kernel2(const int2* __restrict__ src_idx,
                                   const int2* __restrict__ dst_idx,
                                   float2* __restrict__ out,
                                   int E2)
{
    const int i = blockIdx.x * blockDim.x + threadIdx.x;
    if (i >= E2) return;
    const int2 s = src_idx[i];
    const int2 d = dst_idx[i];
    float2 r;
    r.x = g_uscore[s.x] + g_iscore[d.x];
    r.y = g_uscore[s.y] + g_iscore[d.y];
    out[i] = r;
}

__global__ void edge_score_tail(const int* __restrict__ src_idx,
                                const int* __restrict__ dst_idx,
                                float* __restrict__ out,
                                int start, int E)
{
    int e = start + threadIdx.x;
    if (e < E)
        out[e] = g_uscore[src_idx[e]] + g_iscore[dst_idx[e]];
}

// ---------------------------------------------------------------------------
// Inputs (metadata order): user_feats f32 [Nu,128], item_feats f32 [Ni,128],
// src_idx i32 [E], dst_idx i32 [E], W f32 [256,1], b f32 [1].
// Output: f32 [E,1].
// ---------------------------------------------------------------------------
extern "C" void kernel_launch(void* const* d_in, const int* in_sizes, int n_in,
                              void* d_out, int out_size)
{
    const float* user_feats = (const float*)d_in[0];
    const float* item_feats = (const float*)d_in[1];
    const int*   src_idx    = (const int*)d_in[2];
    const int*   dst_idx    = (const int*)d_in[3];
    const float* W          = (const float*)d_in[4];
    const float* b          = (const float*)d_in[5];
    float*       out        = (float*)d_out;

    const int Nu = in_sizes[0] / 128;
    const int Ni = in_sizes[1] / 128;
    const int E  = in_sizes[2];

    // Kernel 1: one warp per two node rows; 8 warps (16 rows) per block.
    {
        const int total_rows = Nu + Ni;
        const int rows_per_block = 16;
        const int blocks = (total_rows + rows_per_block - 1) / rows_per_block;
        node_score_kernel<<<blocks, 256>>>(user_feats, item_feats, W, b, Nu, Ni);
    }

    // Kernel 2: smem-staged u-table if it fits, else fallback gather.
    const int E2 = E / 2;
    const size_t smem_bytes = (size_t)Nu * sizeof(float);
    if (smem_bytes <= 220 * 1024) {
        static bool attr_set = false;
        if (!attr_set) {
            cudaFuncSetAttribute(edge_score_smem,
                                 cudaFuncAttributeMaxDynamicSharedMemorySize,
                                 227 * 1024);
            attr_set = true;
        }
        edge_score_smem<<<148, 1024, smem_bytes>>>(
            (const int2*)src_idx, (const int2*)dst_idx,
            src_idx, dst_idx, out, Nu, E2, E);
    } else {
        if (E2 > 0) {
            const int threads = 256;
            const int blocks = (E2 + threads - 1) / threads;
            edge_score_kernel2<<<blocks, threads>>>(
                (const int2*)src_idx, (const int2*)dst_idx, (float2*)out, E2);
        }
        if (E - E2 * 2 > 0)
            edge_score_tail<<<1, 32>>>(src_idx, dst_idx, out, E2 * 2, E);
    }
}

// round 7
// speedup vs baseline: 1.1235x; 1.1235x over previous
#include <cuda_runtime.h>
#include <cuda_bf16.h>

#define MAX_NODES 65536
#define NB 148          // persistent grid: one block per SM (GB300 has 152 SMs)
#define NT 1024
#define SPLIT_I 64      // phase B: blocks [0,SPLIT_I) -> i-scores, rest -> edge-u

__device__ float g_uscore[MAX_NODES];   // + bias folded in
__device__ float g_iscore[MAX_NODES];
__device__ unsigned g_bar_count;        // monotonic across barriers AND launches

// Monotonic grid barrier: each barrier consumes NB arrivals; no reset needed,
// deterministic and safe across graph replays (only relative counts used).
__device__ __forceinline__ void grid_barrier()
{
    __syncthreads();
    if (threadIdx.x == 0) {
        __threadfence();
        const unsigned a = atomicAdd(&g_bar_count, 1u);
        const unsigned target = (a / NB + 1u) * NB;
        volatile unsigned* vc = &g_bar_count;
        while (*vc < target) { }
        __threadfence();
    }
    __syncthreads();
}

__device__ __forceinline__ float warp_reduce(float s)
{
    #pragma unroll
    for (int o = 16; o > 0; o >>= 1)
        s += __shfl_xor_sync(0xffffffffu, s, o);
    return s;
}

__global__ __launch_bounds__(NT, 1)
void fused_kernel(const float* __restrict__ user_feats,
                  const float* __restrict__ item_feats,
                  const int*   __restrict__ src_idx,
                  const int*   __restrict__ dst_idx,
                  const float* __restrict__ W,
                  const float* __restrict__ b,
                  float* __restrict__ out,
                  int Nu, int Ni, int E)
{
    const int wib   = threadIdx.x >> 5;
    const int lane  = threadIdx.x & 31;
    const int gwarp = blockIdx.x * (NT / 32) + wib;
    const int nwarp = NB * (NT / 32);

    const float4* Wu = reinterpret_cast<const float4*>(W);        // W[0:128]
    const float4* Wi = Wu + 32;                                   // W[128:256]
    const float4 wu = Wu[lane];
    const float4 wi = Wi[lane];
    const float bias = b[0];

    // ---------------- Phase A: u-scores (all blocks), 2 rows per warp-task --
    {
        const int ntask = (Nu + 1) >> 1;
        for (int t = gwarp; t < ntask; t += nwarp) {
            const int r0 = 2 * t;
            const int r1 = r0 + 1;
            const float4* f0 = reinterpret_cast<const float4*>(user_feats) + (size_t)r0 * 32;
            const float4 v0 = f0[lane];
            float s0 = v0.x * wu.x + v0.y * wu.y + v0.z * wu.z + v0.w * wu.w;
            float s1 = 0.0f;
            if (r1 < Nu) {
                const float4* f1 = reinterpret_cast<const float4*>(user_feats) + (size_t)r1 * 32;
                const float4 v1 = f1[lane];
                s1 = v1.x * wu.x + v1.y * wu.y + v1.z * wu.z + v1.w * wu.w;
            }
            s0 = warp_reduce(s0);
            s1 = warp_reduce(s1);
            if (lane == 0) {
                g_uscore[r0] = s0 + bias;
                if (r1 < Nu) g_uscore[r1] = s1 + bias;
            }
        }
    }
    grid_barrier();

    // ---------------- Phase B: i-scores (blocks [0,SPLIT_I)) in parallel with
    // ----------------          edge-u gathers (blocks [SPLIT_I,NB)) ---------
    if (blockIdx.x < SPLIT_I) {
        const int lwarp = blockIdx.x * (NT / 32) + wib;
        const int lnw   = SPLIT_I * (NT / 32);
        const int ntask = (Ni + 1) >> 1;
        for (int t = lwarp; t < ntask; t += lnw) {
            const int r0 = 2 * t;
            const int r1 = r0 + 1;
            const float4* f0 = reinterpret_cast<const float4*>(item_feats) + (size_t)r0 * 32;
            const float4 v0 = f0[lane];
            float s0 = v0.x * wi.x + v0.y * wi.y + v0.z * wi.z + v0.w * wi.w;
            float s1 = 0.0f;
            if (r1 < Ni) {
                const float4* f1 = reinterpret_cast<const float4*>(item_feats) + (size_t)r1 * 32;
                const float4 v1 = f1[lane];
                s1 = v1.x * wi.x + v1.y * wi.y + v1.z * wi.z + v1.w * wi.w;
            }
            s0 = warp_reduce(s0);
            s1 = warp_reduce(s1);
            if (lane == 0) {
                g_iscore[r0] = s0;
                if (r1 < Ni) g_iscore[r1] = s1;
            }
        }
    } else {
        // edge-u: out[e] = g_uscore[src[e]]   (bias already folded in)
        const int  ltid = (blockIdx.x - SPLIT_I) * NT + threadIdx.x;
        const int  lnt  = (NB - SPLIT_I) * NT;
        const int  E2   = E >> 1;
        const int2* s2  = reinterpret_cast<const int2*>(src_idx);
        float2*     o2  = reinterpret_cast<float2*>(out);
        for (int i = ltid; i < E2; i += lnt) {
            const int2 s = s2[i];
            float2 r;
            r.x = g_uscore[s.x];
            r.y = g_uscore[s.y];
            o2[i] = r;
        }
        if (ltid == 0 && (E & 1))
            out[E - 1] = g_uscore[src_idx[E - 1]];
    }
    grid_barrier();

    // ---------------- Phase C: out[e] += g_iscore[dst[e]] (all blocks) ------
    {
        const int  tid = blockIdx.x * NT + threadIdx.x;
        const int  nt  = NB * NT;
        const int  E2  = E >> 1;
        const int2* d2 = reinterpret_cast<const int2*>(dst_idx);
        float2*     o2 = reinterpret_cast<float2*>(out);
        for (int i = tid; i < E2; i += nt) {
            const int2 d = d2[i];
            float2 r = o2[i];
            r.x += g_iscore[d.x];
            r.y += g_iscore[d.y];
            o2[i] = r;
        }
        if (tid == 0 && (E & 1))
            out[E - 1] += g_iscore[dst_idx[E - 1]];
    }
}

// ---------------------------------------------------------------------------
// Inputs (metadata order): user_feats f32 [Nu,128], item_feats f32 [Ni,128],
// src_idx i32 [E], dst_idx i32 [E], W f32 [256,1], b f32 [1].
// Output: f32 [E,1].
// ---------------------------------------------------------------------------
extern "C" void kernel_launch(void* const* d_in, const int* in_sizes, int n_in,
                              void* d_out, int out_size)
{
    const float* user_feats = (const float*)d_in[0];
    const float* item_feats = (const float*)d_in[1];
    const int*   src_idx    = (const int*)d_in[2];
    const int*   dst_idx    = (const int*)d_in[3];
    const float* W          = (const float*)d_in[4];
    const float* b          = (const float*)d_in[5];
    float*       out        = (float*)d_out;

    const int Nu = in_sizes[0] / 128;
    const int Ni = in_sizes[1] / 128;
    const int E  = in_sizes[2];

    fused_kernel<<<NB, NT>>>(user_feats, item_feats, src_idx, dst_idx,
                             W, b, out, Nu, Ni, E);
}

// round 8
// speedup vs baseline: 1.2388x; 1.1026x over previous
#include <cuda_runtime.h>
#include <cuda_bf16.h>

#define MAX_NODES 65536
__device__ float g_uscore[MAX_NODES];   // bias folded in
__device__ float g_iscore[MAX_NODES];

__device__ __forceinline__ float warp_reduce(float s)
{
    #pragma unroll
    for (int o = 16; o > 0; o >>= 1)
        s += __shfl_xor_sync(0xffffffffu, s, o);
    return s;
}

// ---------------------------------------------------------------------------
// Node dot products: one warp per TWO rows (2 independent float4 streams).
// ---------------------------------------------------------------------------
__global__ void node_u_kernel(const float* __restrict__ feats,
                              const float* __restrict__ W,
                              const float* __restrict__ b,
                              int N)
{
    const int warp = blockIdx.x * (blockDim.x >> 5) + (threadIdx.x >> 5);
    const int lane = threadIdx.x & 31;
    const int r0 = warp * 2;
    if (r0 >= N) return;
    const int r1 = r0 + 1;

    const float4 w = reinterpret_cast<const float4*>(W)[lane];   // W[0:128]
    const float4 v0 = (reinterpret_cast<const float4*>(feats) + (size_t)r0 * 32)[lane];
    float s0 = v0.x * w.x + v0.y * w.y + v0.z * w.z + v0.w * w.w;
    float s1 = 0.0f;
    if (r1 < N) {
        const float4 v1 = (reinterpret_cast<const float4*>(feats) + (size_t)r1 * 32)[lane];
        s1 = v1.x * w.x + v1.y * w.y + v1.z * w.z + v1.w * w.w;
    }
    s0 = warp_reduce(s0);
    s1 = warp_reduce(s1);
    if (lane == 0) {
        const float bias = b[0];
        g_uscore[r0] = s0 + bias;
        if (r1 < N) g_uscore[r1] = s1 + bias;
    }
}

__global__ void node_i_kernel(const float* __restrict__ feats,
                              const float* __restrict__ W,
                              int N)
{
    const int warp = blockIdx.x * (blockDim.x >> 5) + (threadIdx.x >> 5);
    const int lane = threadIdx.x & 31;
    const int r0 = warp * 2;
    if (r0 >= N) return;
    const int r1 = r0 + 1;

    const float4 w = (reinterpret_cast<const float4*>(W) + 32)[lane];  // W[128:256]
    const float4 v0 = (reinterpret_cast<const float4*>(feats) + (size_t)r0 * 32)[lane];
    float s0 = v0.x * w.x + v0.y * w.y + v0.z * w.z + v0.w * w.w;
    float s1 = 0.0f;
    if (r1 < N) {
        const float4 v1 = (reinterpret_cast<const float4*>(feats) + (size_t)r1 * 32)[lane];
        s1 = v1.x * w.x + v1.y * w.y + v1.z * w.z + v1.w * w.w;
    }
    s0 = warp_reduce(s0);
    s1 = warp_reduce(s1);
    if (lane == 0) {
        g_iscore[r0] = s0;
        if (r1 < N) g_iscore[r1] = s1;
    }
}

// ---------------------------------------------------------------------------
// Edge pass 1: out[e] = u[src[e]]   (2 edges/thread; runs concurrent w/ nodeI)
// ---------------------------------------------------------------------------
__global__ void edge_u_kernel(const int2* __restrict__ src2,
                              const int* __restrict__ src_idx,
                              float* __restrict__ out,
                              int E2, int E)
{
    const int i = blockIdx.x * blockDim.x + threadIdx.x;
    if (i < E2) {
        const int2 s = src2[i];
        float2 r;
        r.x = g_uscore[s.x];
        r.y = g_uscore[s.y];
        reinterpret_cast<float2*>(out)[i] = r;
    }
    if (i == 0 && (E & 1))
        out[E - 1] = g_uscore[src_idx[E - 1]];
}

// ---------------------------------------------------------------------------
// Edge pass 2: out[e] += i[dst[e]]
// ---------------------------------------------------------------------------
__global__ void edge_add_kernel(const int2* __restrict__ dst2,
                                const int* __restrict__ dst_idx,
                                float* __restrict__ out,
                                int E2, int E)
{
    const int i = blockIdx.x * blockDim.x + threadIdx.x;
    if (i < E2) {
        const int2 d = dst2[i];
        float2 r = reinterpret_cast<float2*>(out)[i];
        r.x += g_iscore[d.x];
        r.y += g_iscore[d.y];
        reinterpret_cast<float2*>(out)[i] = r;
    }
    if (i == 0 && (E & 1))
        out[E - 1] += g_iscore[dst_idx[E - 1]];
}

// ---------------------------------------------------------------------------
// Inputs (metadata order): user_feats f32 [Nu,128], item_feats f32 [Ni,128],
// src_idx i32 [E], dst_idx i32 [E], W f32 [256,1], b f32 [1].
// Output: f32 [E,1].
//
// Graph shape (fork/join on the captured default stream):
//   nodeU ──┬── edgeU ─────────┬── edgeAdd
//           └── nodeI (side) ──┘
// nodeI (DRAM-bound) overlaps edgeU (L1tex gather-bound).
// ---------------------------------------------------------------------------
extern "C" void kernel_launch(void* const* d_in, const int* in_sizes, int n_in,
                              void* d_out, int out_size)
{
    const float* user_feats = (const float*)d_in[0];
    const float* item_feats = (const float*)d_in[1];
    const int*   src_idx    = (const int*)d_in[2];
    const int*   dst_idx    = (const int*)d_in[3];
    const float* W          = (const float*)d_in[4];
    const float* b          = (const float*)d_in[5];
    float*       out        = (float*)d_out;

    const int Nu = in_sizes[0] / 128;
    const int Ni = in_sizes[1] / 128;
    const int E  = in_sizes[2];
    const int E2 = E / 2;

    static cudaStream_t s_side = nullptr;
    static cudaEvent_t  e_fork = nullptr, e_join = nullptr;
    if (s_side == nullptr) {
        cudaStreamCreateWithFlags(&s_side, cudaStreamNonBlocking);
        cudaEventCreateWithFlags(&e_fork, cudaEventDisableTiming);
        cudaEventCreateWithFlags(&e_join, cudaEventDisableTiming);
    }

    const int node_tpb = 256;                       // 8 warps -> 16 rows/block
    const int ublocks = (Nu + 15) / 16;
    const int iblocks = (Ni + 15) / 16;
    const int edge_tpb = 256;
    const int eblocks = (E2 + edge_tpb - 1) / edge_tpb;

    bool forked = (s_side != nullptr && e_fork != nullptr && e_join != nullptr);

    // 1) u-scores on the main (captured) stream.
    node_u_kernel<<<ublocks, node_tpb, 0, 0>>>(user_feats, W, b, Nu);

    if (forked) {
        // 2) fork: i-scores on the side stream, concurrent with edgeU below.
        cudaEventRecord(e_fork, 0);
        cudaStreamWaitEvent(s_side, e_fork, 0);
        node_i_kernel<<<iblocks, node_tpb, 0, s_side>>>(item_feats, W, Ni);
        cudaEventRecord(e_join, s_side);

        // 3) edgeU on the main stream (overlaps nodeI).
        edge_u_kernel<<<eblocks, edge_tpb, 0, 0>>>(
            (const int2*)src_idx, src_idx, out, E2, E);

        // 4) join, then edgeAdd.
        cudaStreamWaitEvent(0, e_join, 0);
        edge_add_kernel<<<eblocks, edge_tpb, 0, 0>>>(
            (const int2*)dst_idx, dst_idx, out, E2, E);
    } else {
        // Fallback: fully serial on the captured stream.
        node_i_kernel<<<iblocks, node_tpb, 0, 0>>>(item_feats, W, Ni);
        edge_u_kernel<<<eblocks, edge_tpb, 0, 0>>>(
            (const int2*)src_idx, src_idx, out, E2, E);
        edge_add_kernel<<<eblocks, edge_tpb, 0, 0>>>(
            (const int2*)dst_idx, dst_idx, out, E2, E);
    }
}

// round 9
// speedup vs baseline: 1.2411x; 1.0019x over previous
#include <cuda_runtime.h>
#include <cuda_bf16.h>

#define MAX_NODES 65536
__device__ float g_uscore[MAX_NODES];   // bias folded in
__device__ float g_iscore[MAX_NODES];

__device__ __forceinline__ float warp_reduce(float s)
{
    #pragma unroll
    for (int o = 16; o > 0; o >>= 1)
        s += __shfl_xor_sync(0xffffffffu, s, o);
    return s;
}

// ---------------------------------------------------------------------------
// Node dot products: one warp per TWO rows (2 independent float4 streams).
// ---------------------------------------------------------------------------
__global__ void node_u_kernel(const float* __restrict__ feats,
                              const float* __restrict__ W,
                              const float* __restrict__ b,
                              int N)
{
    const int warp = blockIdx.x * (blockDim.x >> 5) + (threadIdx.x >> 5);
    const int lane = threadIdx.x & 31;
    const int r0 = warp * 2;
    if (r0 >= N) return;
    const int r1 = r0 + 1;

    const float4 w = reinterpret_cast<const float4*>(W)[lane];   // W[0:128]
    const float4 v0 = (reinterpret_cast<const float4*>(feats) + (size_t)r0 * 32)[lane];
    float s0 = v0.x * w.x + v0.y * w.y + v0.z * w.z + v0.w * w.w;
    float s1 = 0.0f;
    if (r1 < N) {
        const float4 v1 = (reinterpret_cast<const float4*>(feats) + (size_t)r1 * 32)[lane];
        s1 = v1.x * w.x + v1.y * w.y + v1.z * w.z + v1.w * w.w;
    }
    s0 = warp_reduce(s0);
    s1 = warp_reduce(s1);
    if (lane == 0) {
        const float bias = b[0];
        g_uscore[r0] = s0 + bias;
        if (r1 < N) g_uscore[r1] = s1 + bias;
    }
}

__global__ void node_i_kernel(const float* __restrict__ feats,
                              const float* __restrict__ W,
                              int N)
{
    const int warp = blockIdx.x * (blockDim.x >> 5) + (threadIdx.x >> 5);
    const int lane = threadIdx.x & 31;
    const int r0 = warp * 2;
    if (r0 >= N) return;
    const int r1 = r0 + 1;

    const float4 w = (reinterpret_cast<const float4*>(W) + 32)[lane];  // W[128:256]
    const float4 v0 = (reinterpret_cast<const float4*>(feats) + (size_t)r0 * 32)[lane];
    float s0 = v0.x * w.x + v0.y * w.y + v0.z * w.z + v0.w * w.w;
    float s1 = 0.0f;
    if (r1 < N) {
        const float4 v1 = (reinterpret_cast<const float4*>(feats) + (size_t)r1 * 32)[lane];
        s1 = v1.x * w.x + v1.y * w.y + v1.z * w.z + v1.w * w.w;
    }
    s0 = warp_reduce(s0);
    s1 = warp_reduce(s1);
    if (lane == 0) {
        g_iscore[r0] = s0;
        if (r1 < N) g_iscore[r1] = s1;
    }
}

// ---------------------------------------------------------------------------
// Edge pass 1: out[e] = u[src[e]]   (2 edges/thread; runs concurrent w/ nodeI)
// ---------------------------------------------------------------------------
__global__ void edge_u_kernel(const int2* __restrict__ src2,
                              const int* __restrict__ src_idx,
                              float* __restrict__ out,
                              int E2, int E)
{
    const int i = blockIdx.x * blockDim.x + threadIdx.x;
    if (i < E2) {
        const int2 s = src2[i];
        float2 r;
        r.x = g_uscore[s.x];
        r.y = g_uscore[s.y];
        reinterpret_cast<float2*>(out)[i] = r;
    }
    if (i == 0 && (E & 1))
        out[E - 1] = g_uscore[src_idx[E - 1]];
}

// ---------------------------------------------------------------------------
// Edge pass 2: out[e] += i[dst[e]]
// ---------------------------------------------------------------------------
__global__ void edge_add_kernel(const int2* __restrict__ dst2,
                                const int* __restrict__ dst_idx,
                                float* __restrict__ out,
                                int E2, int E)
{
    const int i = blockIdx.x * blockDim.x + threadIdx.x;
    if (i < E2) {
        const int2 d = dst2[i];
        float2 r = reinterpret_cast<float2*>(out)[i];
        r.x += g_iscore[d.x];
        r.y += g_iscore[d.y];
        reinterpret_cast<float2*>(out)[i] = r;
    }
    if (i == 0 && (E & 1))
        out[E - 1] += g_iscore[dst_idx[E - 1]];
}

// ---------------------------------------------------------------------------
// Inputs (metadata order): user_feats f32 [Nu,128], item_feats f32 [Ni,128],
// src_idx i32 [E], dst_idx i32 [E], W f32 [256,1], b f32 [1].
// Output: f32 [E,1].
//
// Graph shape (fork/join on the captured default stream):
//   nodeU ──┬── edgeU ─────────┬── edgeAdd
//           └── nodeI (side) ──┘
// nodeI (DRAM-bound) overlaps edgeU (L1tex gather-bound).
// ---------------------------------------------------------------------------
extern "C" void kernel_launch(void* const* d_in, const int* in_sizes, int n_in,
                              void* d_out, int out_size)
{
    const float* user_feats = (const float*)d_in[0];
    const float* item_feats = (const float*)d_in[1];
    const int*   src_idx    = (const int*)d_in[2];
    const int*   dst_idx    = (const int*)d_in[3];
    const float* W          = (const float*)d_in[4];
    const float* b          = (const float*)d_in[5];
    float*       out        = (float*)d_out;

    const int Nu = in_sizes[0] / 128;
    const int Ni = in_sizes[1] / 128;
    const int E  = in_sizes[2];
    const int E2 = E / 2;

    static cudaStream_t s_side = nullptr;
    static cudaEvent_t  e_fork = nullptr, e_join = nullptr;
    if (s_side == nullptr) {
        cudaStreamCreateWithFlags(&s_side, cudaStreamNonBlocking);
        cudaEventCreateWithFlags(&e_fork, cudaEventDisableTiming);
        cudaEventCreateWithFlags(&e_join, cudaEventDisableTiming);
    }

    const int node_tpb = 256;                       // 8 warps -> 16 rows/block
    const int ublocks = (Nu + 15) / 16;
    const int iblocks = (Ni + 15) / 16;
    const int edge_tpb = 256;
    const int eblocks = (E2 + edge_tpb - 1) / edge_tpb;

    bool forked = (s_side != nullptr && e_fork != nullptr && e_join != nullptr);

    // 1) u-scores on the main (captured) stream.
    node_u_kernel<<<ublocks, node_tpb, 0, 0>>>(user_feats, W, b, Nu);

    if (forked) {
        // 2) fork: i-scores on the side stream, concurrent with edgeU below.
        cudaEventRecord(e_fork, 0);
        cudaStreamWaitEvent(s_side, e_fork, 0);
        node_i_kernel<<<iblocks, node_tpb, 0, s_side>>>(item_feats, W, Ni);
        cudaEventRecord(e_join, s_side);

        // 3) edgeU on the main stream (overlaps nodeI).
        edge_u_kernel<<<eblocks, edge_tpb, 0, 0>>>(
            (const int2*)src_idx, src_idx, out, E2, E);

        // 4) join, then edgeAdd.
        cudaStreamWaitEvent(0, e_join, 0);
        edge_add_kernel<<<eblocks, edge_tpb, 0, 0>>>(
            (const int2*)dst_idx, dst_idx, out, E2, E);
    } else {
        // Fallback: fully serial on the captured stream.
        node_i_kernel<<<iblocks, node_tpb, 0, 0>>>(item_feats, W, Ni);
        edge_u_kernel<<<eblocks, edge_tpb, 0, 0>>>(
            (const int2*)src_idx, src_idx, out, E2, E);
        edge_add_kernel<<<eblocks, edge_tpb, 0, 0>>>(
            (const int2*)dst_idx, dst_idx, out, E2, E);
    }
}

// round 10
// speedup vs baseline: 1.2600x; 1.0152x over previous
#include <cuda_runtime.h>
#include <cuda_bf16.h>

#define MAX_NODES   65536
#define NB          444      // 3 blocks/SM * 148 SMs — all resident (guaranteed by launch_bounds)
#define NT          512      // 16 warps/block
#define GATHER_WPB  2        // warps 14,15 of each block do edge gathers in phase B
#define STREAM_WPB  (16 - GATHER_WPB)
#define NGW         (NB * GATHER_WPB)          // 888 gather warps
#define EPW         12                          // edges per lane (888*32*12 = 341k >= E)

__device__ float g_uscore[MAX_NODES];   // bias folded in
__device__ float g_iscore[MAX_NODES];
__device__ unsigned g_bar_count;        // monotonic across barriers AND graph replays

// Monotonic grid barrier (no reset; only relative counts used -> replay-safe).
__device__ __forceinline__ void grid_barrier()
{
    __syncthreads();
    if (threadIdx.x == 0) {
        __threadfence();
        const unsigned a = atomicAdd(&g_bar_count, 1u);
        const unsigned target = (a / NB + 1u) * NB;
        volatile unsigned* vc = &g_bar_count;
        while (*vc < target) { }
        __threadfence();
    }
    __syncthreads();
}

__device__ __forceinline__ float warp_reduce(float s)
{
    #pragma unroll
    for (int o = 16; o > 0; o >>= 1)
        s += __shfl_xor_sync(0xffffffffu, s, o);
    return s;
}

// Stream 2 rows per warp-task: score[r] = dot(feats[r], w) (+bias), grid-stride.
__device__ __forceinline__ void stream_rows(const float* __restrict__ feats,
                                            const float4 w, const float bias,
                                            float* __restrict__ table,
                                            int N, int warp_id, int nwarps, int lane)
{
    const int ntask = (N + 1) >> 1;
    for (int t = warp_id; t < ntask; t += nwarps) {
        const int r0 = 2 * t;
        const int r1 = r0 + 1;
        const float4 v0 = (reinterpret_cast<const float4*>(feats) + (size_t)r0 * 32)[lane];
        float s0 = v0.x * w.x + v0.y * w.y + v0.z * w.z + v0.w * w.w;
        float s1 = 0.0f;
        if (r1 < N) {
            const float4 v1 = (reinterpret_cast<const float4*>(feats) + (size_t)r1 * 32)[lane];
            s1 = v1.x * w.x + v1.y * w.y + v1.z * w.z + v1.w * w.w;
        }
        s0 = warp_reduce(s0);
        s1 = warp_reduce(s1);
        if (lane == 0) {
            table[r0] = s0 + bias;
            if (r1 < N) table[r1] = s1 + bias;
        }
    }
}

__global__ __launch_bounds__(NT, 3)
void fused_kernel(const float* __restrict__ user_feats,
                  const float* __restrict__ item_feats,
                  const int*   __restrict__ src_idx,
                  const int*   __restrict__ dst_idx,
                  const float* __restrict__ W,
                  const float* __restrict__ b,
                  float* __restrict__ out,
                  int Nu, int Ni, int E)
{
    const int wib  = threadIdx.x >> 5;          // warp in block, 0..15
    const int lane = threadIdx.x & 31;

    const float4 wu = reinterpret_cast<const float4*>(W)[lane];        // W[0:128]
    const float4 wi = (reinterpret_cast<const float4*>(W) + 32)[lane]; // W[128:256]
    const float bias = b[0];

    // ---- Phase A: u-scores, all warps ----------------------------------
    {
        const int gw = blockIdx.x * 16 + wib;
        stream_rows(user_feats, wu, bias, g_uscore, Nu, gw, NB * 16, lane);
    }
    grid_barrier();

    // ---- Phase B: per-block warp split ---------------------------------
    const bool is_gather = (wib >= STREAM_WPB);
    float vals[EPW];

    if (!is_gather) {
        // i-scores on 14/16 warps of every block (DRAM-bound).
        const int sw = blockIdx.x * STREAM_WPB + wib;
        stream_rows(item_feats, wi, 0.0f, g_iscore, Ni, sw, NB * STREAM_WPB, lane);
    } else {
        // u-gathers into registers (L1tex-bound), strided-coalesced layout.
        const int gwid = blockIdx.x * GATHER_WPB + (wib - STREAM_WPB); // 0..NGW-1
        const int base = gwid * 32 + lane;
        #pragma unroll
        for (int j = 0; j < EPW; j++) {
            const int e = base + j * (NGW * 32);
            vals[j] = (e < E) ? g_uscore[src_idx[e]] : 0.0f;
        }
    }
    grid_barrier();

    // ---- Phase C: gather warps finish edges; stream warps exit ----------
    if (is_gather) {
        const int gwid = blockIdx.x * GATHER_WPB + (wib - STREAM_WPB);
        const int base = gwid * 32 + lane;
        #pragma unroll
        for (int j = 0; j < EPW; j++) {
            const int e = base + j * (NGW * 32);
            if (e < E)
                out[e] = vals[j] + g_iscore[dst_idx[e]];
        }
    }
}

// ---------------------------------------------------------------------------
// Inputs (metadata order): user_feats f32 [Nu,128], item_feats f32 [Ni,128],
// src_idx i32 [E], dst_idx i32 [E], W f32 [256,1], b f32 [1].
// Output: f32 [E,1].
// ---------------------------------------------------------------------------
extern "C" void kernel_launch(void* const* d_in, const int* in_sizes, int n_in,
                              void* d_out, int out_size)
{
    const float* user_feats = (const float*)d_in[0];
    const float* item_feats = (const float*)d_in[1];
    const int*   src_idx    = (const int*)d_in[2];
    const int*   dst_idx    = (const int*)d_in[3];
    const float* W          = (const float*)d_in[4];
    const float* b          = (const float*)d_in[5];
    float*       out        = (float*)d_out;

    const int Nu = in_sizes[0] / 128;
    const int Ni = in_sizes[1] / 128;
    const int E  = in_sizes[2];

    fused_kernel<<<NB, NT>>>(user_feats, item_feats, src_idx, dst_idx,
                             W, b, out, Nu, Ni, E);
}